// round 3
// baseline (speedup 1.0000x reference)
#include <cuda_runtime.h>
#include <cstddef>

#define BSZ 8
#define SEQ 512
#define DIM 768
#define RNK 128
#define MTOT (BSZ * SEQ)   // 4096

// Scratch (device globals — no allocation allowed)
__device__ float g_Pd[MTOT * RNK];     // P_dist   (4096 x 128)
__device__ float g_norms[MTOT];        // row sumsq of P_dist

// ---------------------------------------------------------------------------
// Kernel 1: projection GEMM  P[m][n] = sum_k emb[m][k] * proj[n][k]
//   M=4096, N=128, K=768. blockIdx.y selects proj_dist / proj_depth.
//   Block tile 64(M) x 128(N), K-tile 32. 256 threads, thread tile 8x4.
//   Smem tiles stored transposed ([k][m], [k][n]) for vector LDS in inner loop.
//   Epilogue fuses the row sum-of-squares: each warp owns 8 full rows
//   (128 cols spread 4-per-lane), so a butterfly shuffle gives the row norm.
//   which==0: store P to g_Pd and norms to g_norms (dist path needs both).
//   which==1: P matrix itself is NOT needed downstream — only depths.
// ---------------------------------------------------------------------------
__global__ __launch_bounds__(256) void proj_kernel(
    const float* __restrict__ emb,
    const float* __restrict__ proj_dist,
    const float* __restrict__ proj_depth,
    float* __restrict__ out_depths)
{
    const int which = blockIdx.y;
    const float* __restrict__ proj = which ? proj_depth : proj_dist;

    __shared__ float AsT[32][68];    // [k][m], padded
    __shared__ float BsT[32][132];   // [k][n], padded

    const int t = threadIdx.x;
    const int m0 = blockIdx.x * 64;
    const int tidN = t % 32;   // cols tidN*4 .. +3
    const int tidM = t / 32;   // rows tidM*8 .. +7

    float acc[8][4];
    #pragma unroll
    for (int i = 0; i < 8; i++)
        #pragma unroll
        for (int j = 0; j < 4; j++) acc[i][j] = 0.f;

    const int kvec = t % 8;    // which float4 of the 32-wide K tile
    const int ldrow = t / 8;   // 0..31

    for (int kt = 0; kt < DIM; kt += 32) {
        // A tile: 64 rows x 32 k  (transposed store)
        #pragma unroll
        for (int rr = 0; rr < 2; rr++) {
            int r = ldrow + rr * 32;
            float4 v = *(const float4*)&emb[(size_t)(m0 + r) * DIM + kt + kvec * 4];
            AsT[kvec * 4 + 0][r] = v.x;
            AsT[kvec * 4 + 1][r] = v.y;
            AsT[kvec * 4 + 2][r] = v.z;
            AsT[kvec * 4 + 3][r] = v.w;
        }
        // B tile: 128 n x 32 k  (transposed store)
        #pragma unroll
        for (int nn = 0; nn < 4; nn++) {
            int nr = ldrow + nn * 32;
            float4 v = *(const float4*)&proj[(size_t)nr * DIM + kt + kvec * 4];
            BsT[kvec * 4 + 0][nr] = v.x;
            BsT[kvec * 4 + 1][nr] = v.y;
            BsT[kvec * 4 + 2][nr] = v.z;
            BsT[kvec * 4 + 3][nr] = v.w;
        }
        __syncthreads();

        #pragma unroll
        for (int kk = 0; kk < 32; kk++) {
            float4 a0 = *(const float4*)&AsT[kk][tidM * 8 + 0];
            float4 a1 = *(const float4*)&AsT[kk][tidM * 8 + 4];
            float4 b  = *(const float4*)&BsT[kk][tidN * 4];
            float av[8] = {a0.x, a0.y, a0.z, a0.w, a1.x, a1.y, a1.z, a1.w};
            float bv[4] = {b.x, b.y, b.z, b.w};
            #pragma unroll
            for (int i = 0; i < 8; i++)
                #pragma unroll
                for (int j = 0; j < 4; j++)
                    acc[i][j] += av[i] * bv[j];
        }
        __syncthreads();
    }

    // Epilogue.
    if (which == 0) {
        // store P (coalesced float4) — needed by the Gram kernel
        #pragma unroll
        for (int i = 0; i < 8; i++) {
            int row = m0 + tidM * 8 + i;
            float4 r = {acc[i][0], acc[i][1], acc[i][2], acc[i][3]};
            *(float4*)&g_Pd[(size_t)row * RNK + tidN * 4] = r;
        }
    }
    // fused row sum-of-squares: each warp = rows tidM*8..+7, cols across lanes
    #pragma unroll
    for (int i = 0; i < 8; i++) {
        float s = acc[i][0] * acc[i][0] + acc[i][1] * acc[i][1]
                + acc[i][2] * acc[i][2] + acc[i][3] * acc[i][3];
        #pragma unroll
        for (int o = 16; o > 0; o >>= 1)
            s += __shfl_xor_sync(0xFFFFFFFFu, s, o);
        if (tidN == 0) {
            int row = m0 + tidM * 8 + i;
            if (which == 0) g_norms[row]   = s;
            else            out_depths[row] = s;
        }
    }
}

// ---------------------------------------------------------------------------
// Kernel 2: distances via Gram matrix.
//   dist[b,i,j] = n_i + n_j - 2 * dot(P_i, P_j),   K=128 (fits smem, no K loop)
//   Block tile 64(i) x 64(j). 256 threads, thread tile 4x4.
//   Tiles stored transposed [k][row] (stride 68) => vector LDS, conflict-free.
// ---------------------------------------------------------------------------
#define LDT 68
__global__ __launch_bounds__(256) void dist_kernel(float* __restrict__ out)
{
    extern __shared__ float sm[];
    float* AiT = sm;                  // [128][68]
    float* AjT = sm + 128 * LDT;      // [128][68]
    float* sNi = AjT + 128 * LDT;     // [64]
    float* sNj = sNi + 64;            // [64]

    const int b  = blockIdx.z;
    const int i0 = blockIdx.y * 64;
    const int j0 = blockIdx.x * 64;
    const float* __restrict__ P = g_Pd + (size_t)b * SEQ * RNK;

    const int t = threadIdx.x;
    const int lrow = t % 32;
    const int lkv  = t / 32;   // 0..7

    // load both 64x128 tiles, transposed into smem (STS conflict-free:
    // within a warp, lanes span 32 consecutive rows -> consecutive banks)
    #pragma unroll
    for (int rr = 0; rr < 2; rr++) {
        int r = lrow + rr * 32;
        #pragma unroll
        for (int kq = 0; kq < 4; kq++) {
            int kv = lkv + kq * 8;
            float4 v = *(const float4*)&P[(size_t)(i0 + r) * RNK + kv * 4];
            AiT[(kv * 4 + 0) * LDT + r] = v.x;
            AiT[(kv * 4 + 1) * LDT + r] = v.y;
            AiT[(kv * 4 + 2) * LDT + r] = v.z;
            AiT[(kv * 4 + 3) * LDT + r] = v.w;
            float4 w = *(const float4*)&P[(size_t)(j0 + r) * RNK + kv * 4];
            AjT[(kv * 4 + 0) * LDT + r] = w.x;
            AjT[(kv * 4 + 1) * LDT + r] = w.y;
            AjT[(kv * 4 + 2) * LDT + r] = w.z;
            AjT[(kv * 4 + 3) * LDT + r] = w.w;
        }
    }
    if (t < 64)       sNi[t]      = g_norms[b * SEQ + i0 + t];
    else if (t < 128) sNj[t - 64] = g_norms[b * SEQ + j0 + (t - 64)];
    __syncthreads();

    const int tidJ = t % 16;   // j cols tidJ*4..+3
    const int tidI = t / 16;   // i rows tidI*4..+3

    float acc[4][4];
    #pragma unroll
    for (int i = 0; i < 4; i++)
        #pragma unroll
        for (int j = 0; j < 4; j++) acc[i][j] = 0.f;

    #pragma unroll 8
    for (int kk = 0; kk < RNK; kk++) {
        float4 a  = *(const float4*)&AiT[kk * LDT + tidI * 4];
        float4 bb = *(const float4*)&AjT[kk * LDT + tidJ * 4];
        float av[4] = {a.x, a.y, a.z, a.w};
        float bv[4] = {bb.x, bb.y, bb.z, bb.w};
        #pragma unroll
        for (int i = 0; i < 4; i++)
            #pragma unroll
            for (int j = 0; j < 4; j++)
                acc[i][j] += av[i] * bv[j];
    }

    // epilogue: dist = n_i + n_j - 2*gram, float4 coalesced stores
    float nj0 = sNj[tidJ * 4 + 0], nj1 = sNj[tidJ * 4 + 1];
    float nj2 = sNj[tidJ * 4 + 2], nj3 = sNj[tidJ * 4 + 3];
    #pragma unroll
    for (int i = 0; i < 4; i++) {
        float ni = sNi[tidI * 4 + i];
        float4 r;
        r.x = ni + nj0 - 2.f * acc[i][0];
        r.y = ni + nj1 - 2.f * acc[i][1];
        r.z = ni + nj2 - 2.f * acc[i][2];
        r.w = ni + nj3 - 2.f * acc[i][3];
        size_t off = (size_t)b * SEQ * SEQ + (size_t)(i0 + tidI * 4 + i) * SEQ
                   + j0 + tidJ * 4;
        *(float4*)&out[off] = r;
    }
}

// ---------------------------------------------------------------------------
extern "C" void kernel_launch(void* const* d_in, const int* in_sizes, int n_in,
                              void* d_out, int out_size)
{
    const float* emb = (const float*)d_in[0];
    const float* pd  = (const float*)d_in[1];
    const float* pt  = (const float*)d_in[2];
    float* out       = (float*)d_out;
    float* out_dist  = out;
    float* out_depth = out + (size_t)BSZ * SEQ * SEQ;

    const int smem3 = (128 * LDT * 2 + 128) * (int)sizeof(float);  // ~70 KB
    cudaFuncSetAttribute(dist_kernel,
                         cudaFuncAttributeMaxDynamicSharedMemorySize, smem3);

    proj_kernel<<<dim3(MTOT / 64, 2), 256>>>(emb, pd, pt, out_depth);
    dist_kernel<<<dim3(SEQ / 64, SEQ / 64, BSZ), 256, smem3>>>(out_dist);
}

// round 13
// speedup vs baseline: 2.2340x; 2.2340x over previous
#include <cuda_runtime.h>
#include <cuda_bf16.h>
#include <cstdint>
#include <cstddef>

#define BSZ 8
#define SEQ 512
#define DIM 768
#define RNK 128
#define MTOT (BSZ * SEQ)   // 4096

// Scratch (device globals — no allocation allowed)
__device__ __nv_bfloat16 g_Phi[MTOT * RNK];  // P_dist hi
__device__ __nv_bfloat16 g_Plo[MTOT * RNK];  // P_dist lo (residual)
__device__ float g_norms[MTOT];              // row sumsq of P_dist (fp32-exact)

// ---------------------------------------------------------------------------
// Warp-MMA helpers (baseline PTX, legal on compute_103)
// ---------------------------------------------------------------------------
__device__ __forceinline__ uint32_t smem_u32(const void* p) {
    uint32_t a;
    asm("{ .reg .u64 t; cvta.to.shared.u64 t, %1; cvt.u32.u64 %0, t; }"
        : "=r"(a) : "l"(p));
    return a;
}

__device__ __forceinline__ void ldsm4(uint32_t addr, uint32_t* r) {
    asm volatile("ldmatrix.sync.aligned.m8n8.x4.shared.b16 {%0,%1,%2,%3}, [%4];"
                 : "=r"(r[0]), "=r"(r[1]), "=r"(r[2]), "=r"(r[3]) : "r"(addr));
}

__device__ __forceinline__ void mma_bf16(float (&c)[4], const uint32_t (&a)[4],
                                         const uint32_t* b) {
    asm volatile(
        "mma.sync.aligned.m16n8k16.row.col.f32.bf16.bf16.f32 "
        "{%0,%1,%2,%3}, {%4,%5,%6,%7}, {%8,%9}, {%0,%1,%2,%3};"
        : "+f"(c[0]), "+f"(c[1]), "+f"(c[2]), "+f"(c[3])
        : "r"(a[0]), "r"(a[1]), "r"(a[2]), "r"(a[3]), "r"(b[0]), "r"(b[1]));
}

// Smem tiles: [rows][72] bf16, pitch 144 B (16B-aligned, odd 16B-multiple
// per 8 rows -> conflict-free ldmatrix; data cols 0..63).
#define PITCH 72

// fp32 [ROWS][64] tile (ld = src row stride) -> hi/lo bf16 smem tiles
template<int ROWS>
__device__ __forceinline__ void stage_split(const float* __restrict__ src, int ld,
                                            char* sm, int off_hi, int off_lo, int t)
{
    #pragma unroll
    for (int i = 0; i < ROWS / 16; i++) {
        int idx = i * 256 + t;
        int row = idx >> 4;
        int c4  = idx & 15;
        float4 v = *(const float4*)&src[(size_t)row * ld + c4 * 4];
        __nv_bfloat16 h0 = __float2bfloat16_rn(v.x);
        __nv_bfloat16 h1 = __float2bfloat16_rn(v.y);
        __nv_bfloat16 h2 = __float2bfloat16_rn(v.z);
        __nv_bfloat16 h3 = __float2bfloat16_rn(v.w);
        __nv_bfloat16 l0 = __float2bfloat16_rn(v.x - __bfloat162float(h0));
        __nv_bfloat16 l1 = __float2bfloat16_rn(v.y - __bfloat162float(h1));
        __nv_bfloat16 l2 = __float2bfloat16_rn(v.z - __bfloat162float(h2));
        __nv_bfloat16 l3 = __float2bfloat16_rn(v.w - __bfloat162float(h3));
        uint2 hp, lp;
        hp.x = (uint32_t)__bfloat16_as_ushort(h0) | ((uint32_t)__bfloat16_as_ushort(h1) << 16);
        hp.y = (uint32_t)__bfloat16_as_ushort(h2) | ((uint32_t)__bfloat16_as_ushort(h3) << 16);
        lp.x = (uint32_t)__bfloat16_as_ushort(l0) | ((uint32_t)__bfloat16_as_ushort(l1) << 16);
        lp.y = (uint32_t)__bfloat16_as_ushort(l2) | ((uint32_t)__bfloat16_as_ushort(l3) << 16);
        int boff = (row * PITCH + c4 * 4) * 2;
        *(uint2*)(sm + off_hi + boff) = hp;
        *(uint2*)(sm + off_lo + boff) = lp;
    }
}

// bf16 [128][64] tile copy (src row stride RNK elements)
__device__ __forceinline__ void stage_copy(const __nv_bfloat16* __restrict__ src,
                                           char* sm, int off, int t)
{
    #pragma unroll
    for (int i = 0; i < 8; i++) {
        int idx = i * 256 + t;
        int row = idx >> 4;
        int c4  = idx & 15;
        uint2 v = *(const uint2*)(src + (size_t)row * RNK + c4 * 4);
        *(uint2*)(sm + off + (row * PITCH + c4 * 4) * 2) = v;
    }
}

// One K=64 chunk: 4 k-steps x (MF m-frags x 4 n-frags x 3 split passes).
// aHi/aLo/bHi/bLo are lane-resolved ldmatrix base addresses at k0=0.
template<int MF>
__device__ __forceinline__ void chunk_mma(uint32_t aHi, uint32_t aLo,
                                          uint32_t bHi, uint32_t bLo,
                                          float (*acc)[4][4])
{
    #pragma unroll
    for (int ks = 0; ks < 4; ks++) {
        uint32_t ah[MF][4], al[MF][4], bh[2][4], bl[2][4];
        #pragma unroll
        for (int mi = 0; mi < MF; mi++) {
            ldsm4(aHi + mi * 16 * (PITCH * 2) + ks * 32, ah[mi]);
            ldsm4(aLo + mi * 16 * (PITCH * 2) + ks * 32, al[mi]);
        }
        #pragma unroll
        for (int nj = 0; nj < 2; nj++) {
            ldsm4(bHi + nj * 16 * (PITCH * 2) + ks * 32, bh[nj]);
            ldsm4(bLo + nj * 16 * (PITCH * 2) + ks * 32, bl[nj]);
        }
        #pragma unroll
        for (int mi = 0; mi < MF; mi++)
            #pragma unroll
            for (int nf = 0; nf < 4; nf++) {
                const uint32_t* ph = &bh[nf >> 1][(nf & 1) * 2];
                const uint32_t* pl = &bl[nf >> 1][(nf & 1) * 2];
                mma_bf16(acc[mi][nf], ah[mi], ph);   // hi*hi
                mma_bf16(acc[mi][nf], ah[mi], pl);   // hi*lo
                mma_bf16(acc[mi][nf], al[mi], ph);   // lo*hi
            }
    }
}

// ---------------------------------------------------------------------------
// Kernel 1: projection GEMM.  P[m][n] = emb[m] . proj[n], M=4096,N=128,K=768.
//   grid (64, 2): x = 64-row M tile, y selects proj_dist / proj_depth.
//   8 warps: wm=wid&1 (32 rows), wn=wid>>1 (32 cols). K: 12 chunks of 64.
//   Epilogue: which==0 -> store P hi/lo bf16 + g_norms; which==1 -> depths.
// ---------------------------------------------------------------------------
#define PA_HI 0
#define PA_LO 9216                    // 64*144
#define PB_HI 18432
#define PB_LO 36864                   // + 128*144
#define PNORM 55296
#define PSM_TOTAL (PNORM + 256)

__global__ __launch_bounds__(256) void proj_mma_kernel(
    const float* __restrict__ emb,
    const float* __restrict__ proj_dist,
    const float* __restrict__ proj_depth,
    float* __restrict__ out_depths)
{
    extern __shared__ char smem[];
    const int t = threadIdx.x;
    const int lane = t & 31, wid = t >> 5;
    const int wm = wid & 1, wn = wid >> 1;
    const int m0 = blockIdx.x * 64;
    const int which = blockIdx.y;
    const float* __restrict__ Bm = which ? proj_depth : proj_dist;
    float* sNorm = (float*)(smem + PNORM);

    if (t < 64) sNorm[t] = 0.f;

    const uint32_t sb = smem_u32(smem);
    const int arow = lane & 15, acol = (lane >> 4) * 8;
    const int brow = (lane & 7) + ((lane >> 4) << 3), bcol = ((lane >> 3) & 1) * 8;
    const uint32_t aHi = sb + PA_HI + ((wm * 32 + arow) * PITCH + acol) * 2;
    const uint32_t aLo = aHi + (PA_LO - PA_HI);
    const uint32_t bHi = sb + PB_HI + ((wn * 32 + brow) * PITCH + bcol) * 2;
    const uint32_t bLo = bHi + (PB_LO - PB_HI);

    float acc[2][4][4];
    #pragma unroll
    for (int mi = 0; mi < 2; mi++)
        #pragma unroll
        for (int nf = 0; nf < 4; nf++)
            #pragma unroll
            for (int k = 0; k < 4; k++) acc[mi][nf][k] = 0.f;

    for (int c = 0; c < 12; c++) {
        stage_split<64>(emb + (size_t)m0 * DIM + c * 64, DIM, smem, PA_HI, PA_LO, t);
        stage_split<128>(Bm + c * 64, DIM, smem, PB_HI, PB_LO, t);
        __syncthreads();
        chunk_mma<2>(aHi, aLo, bHi, bLo, acc);
        __syncthreads();
    }

    // Epilogue: store P hi/lo + fused row norms.
    #pragma unroll
    for (int mi = 0; mi < 2; mi++) {
        #pragma unroll
        for (int h = 0; h < 2; h++) {
            int rowl = wm * 32 + mi * 16 + (lane >> 2) + h * 8;
            float s = 0.f;
            #pragma unroll
            for (int nf = 0; nf < 4; nf++) {
                float v0 = acc[mi][nf][h * 2 + 0];
                float v1 = acc[mi][nf][h * 2 + 1];
                s += v0 * v0 + v1 * v1;
                if (which == 0) {
                    int col = wn * 32 + nf * 8 + (lane & 3) * 2;
                    __nv_bfloat16 h0 = __float2bfloat16_rn(v0);
                    __nv_bfloat16 h1 = __float2bfloat16_rn(v1);
                    __nv_bfloat16 l0 = __float2bfloat16_rn(v0 - __bfloat162float(h0));
                    __nv_bfloat16 l1 = __float2bfloat16_rn(v1 - __bfloat162float(h1));
                    uint32_t hp = (uint32_t)__bfloat16_as_ushort(h0)
                                | ((uint32_t)__bfloat16_as_ushort(h1) << 16);
                    uint32_t lp = (uint32_t)__bfloat16_as_ushort(l0)
                                | ((uint32_t)__bfloat16_as_ushort(l1) << 16);
                    size_t o = (size_t)(m0 + rowl) * RNK + col;
                    *(uint32_t*)&g_Phi[o] = hp;
                    *(uint32_t*)&g_Plo[o] = lp;
                }
            }
            s += __shfl_xor_sync(0xFFFFFFFFu, s, 1);
            s += __shfl_xor_sync(0xFFFFFFFFu, s, 2);
            if ((lane & 3) == 0) atomicAdd(&sNorm[rowl], s);
        }
    }
    __syncthreads();
    if (t < 64) {
        if (which == 0) g_norms[m0 + t]   = sNorm[t];
        else            out_depths[m0 + t] = sNorm[t];
    }
}

// ---------------------------------------------------------------------------
// Kernel 2: distances.  dist[b,i,j] = n_i + n_j - 2 * P_i.P_j, K=128.
//   grid (4,4,8), 128x128 tile per CTA, 8 warps: wm (64 rows), wn (32 cols).
// ---------------------------------------------------------------------------
#define GA_HI 0
#define GA_LO 18432                   // 128*144
#define GB_HI 36864
#define GB_LO 55296
#define GNI   73728
#define GNJ   (GNI + 512)
#define GSM_TOTAL (GNJ + 512)

__global__ __launch_bounds__(256) void gram_kernel(float* __restrict__ out)
{
    extern __shared__ char smem[];
    const int t = threadIdx.x;
    const int lane = t & 31, wid = t >> 5;
    const int wm = wid & 1, wn = wid >> 1;
    const int b  = blockIdx.z;
    const int i0 = blockIdx.y * 128;
    const int j0 = blockIdx.x * 128;
    float* sNi = (float*)(smem + GNI);
    float* sNj = (float*)(smem + GNJ);

    if (t < 128)      sNi[t]       = g_norms[b * SEQ + i0 + t];
    else              sNj[t - 128] = g_norms[b * SEQ + j0 + (t - 128)];

    const uint32_t sb = smem_u32(smem);
    const int arow = lane & 15, acol = (lane >> 4) * 8;
    const int brow = (lane & 7) + ((lane >> 4) << 3), bcol = ((lane >> 3) & 1) * 8;
    const uint32_t aHi = sb + GA_HI + ((wm * 64 + arow) * PITCH + acol) * 2;
    const uint32_t aLo = aHi + (GA_LO - GA_HI);
    const uint32_t bHi = sb + GB_HI + ((wn * 32 + brow) * PITCH + bcol) * 2;
    const uint32_t bLo = bHi + (GB_LO - GB_HI);

    const size_t baseI = ((size_t)b * SEQ + i0) * RNK;
    const size_t baseJ = ((size_t)b * SEQ + j0) * RNK;

    float acc[4][4][4];
    #pragma unroll
    for (int mi = 0; mi < 4; mi++)
        #pragma unroll
        for (int nf = 0; nf < 4; nf++)
            #pragma unroll
            for (int k = 0; k < 4; k++) acc[mi][nf][k] = 0.f;

    #pragma unroll
    for (int c = 0; c < 2; c++) {
        stage_copy(g_Phi + baseI + c * 64, smem, GA_HI, t);
        stage_copy(g_Plo + baseI + c * 64, smem, GA_LO, t);
        stage_copy(g_Phi + baseJ + c * 64, smem, GB_HI, t);
        stage_copy(g_Plo + baseJ + c * 64, smem, GB_LO, t);
        __syncthreads();
        chunk_mma<4>(aHi, aLo, bHi, bLo, acc);
        __syncthreads();
    }

    // Epilogue: dist = n_i + n_j - 2*gram, float2 stores.
    #pragma unroll
    for (int mi = 0; mi < 4; mi++) {
        #pragma unroll
        for (int h = 0; h < 2; h++) {
            int rowl = wm * 64 + mi * 16 + (lane >> 2) + h * 8;
            float ni = sNi[rowl];
            #pragma unroll
            for (int nf = 0; nf < 4; nf++) {
                int coll = wn * 32 + nf * 8 + (lane & 3) * 2;
                float2 v;
                v.x = ni + sNj[coll + 0] - 2.f * acc[mi][nf][h * 2 + 0];
                v.y = ni + sNj[coll + 1] - 2.f * acc[mi][nf][h * 2 + 1];
                size_t o = (size_t)b * SEQ * SEQ + (size_t)(i0 + rowl) * SEQ + j0 + coll;
                *(float2*)&out[o] = v;
            }
        }
    }
}

// ---------------------------------------------------------------------------
extern "C" void kernel_launch(void* const* d_in, const int* in_sizes, int n_in,
                              void* d_out, int out_size)
{
    const float* emb = (const float*)d_in[0];
    const float* pd  = (const float*)d_in[1];
    const float* pt  = (const float*)d_in[2];
    float* out       = (float*)d_out;
    float* out_dist  = out;
    float* out_depth = out + (size_t)BSZ * SEQ * SEQ;

    cudaFuncSetAttribute(proj_mma_kernel,
                         cudaFuncAttributeMaxDynamicSharedMemorySize, PSM_TOTAL);
    cudaFuncSetAttribute(gram_kernel,
                         cudaFuncAttributeMaxDynamicSharedMemorySize, GSM_TOTAL);

    proj_mma_kernel<<<dim3(MTOT / 64, 2), 256, PSM_TOTAL>>>(emb, pd, pt, out_depth);
    gram_kernel<<<dim3(SEQ / 128, SEQ / 128, BSZ), 256, GSM_TOTAL>>>(out_dist);
}